// round 5
// baseline (speedup 1.0000x reference)
#include <cuda_runtime.h>
#include <cstdint>

// ---------------------------------------------------------------------------
//   x:[64,1024,512] fp32, w_qkv:[512,1536], w_proj:[512,512], b_proj:[512]
//   out:[64,1024,512]. Token n = h*64+w on 16x64 grid, window |dh|<=3,|dw|<=5.
// ---------------------------------------------------------------------------

#define NTOK   1024
#define BATCH  64
#define MTOT   (BATCH * NTOK)      // 65536
#define DIMSZ  512
#define QKVC   1536

static __device__ float g_qkv[(size_t)MTOT * QKVC];     // 402 MB (tf32 values)
static __device__ float g_att[(size_t)MTOT * DIMSZ];    // 134 MB (tf32 values)
static __device__ float g_xtf[(size_t)MTOT * DIMSZ];    // 134 MB (tf32 of x)
static __device__ float g_wqkvT[QKVC * DIMSZ];          // transposed + tf32
static __device__ float g_wprojT[DIMSZ * DIMSZ];

// ---------------------------------------------------------------------------
__device__ __forceinline__ uint32_t f2tf(float f) {
    uint32_t u;
    asm("cvt.rna.tf32.f32 %0, %1;" : "=r"(u) : "f"(f));
    return u;
}
__device__ __forceinline__ void mma8(float* c, const uint32_t* a,
                                     uint32_t b0, uint32_t b1) {
    asm volatile(
        "mma.sync.aligned.m16n8k8.row.col.f32.tf32.tf32.f32 "
        "{%0,%1,%2,%3}, {%4,%5,%6,%7}, {%8,%9}, {%0,%1,%2,%3};"
        : "+f"(c[0]), "+f"(c[1]), "+f"(c[2]), "+f"(c[3])
        : "r"(a[0]), "r"(a[1]), "r"(a[2]), "r"(a[3]), "r"(b0), "r"(b1));
}
__device__ __forceinline__ void ldsm4(uint32_t addr, uint32_t* r) {
    asm volatile("ldmatrix.sync.aligned.m8n8.x4.shared.b16 {%0,%1,%2,%3}, [%4];"
                 : "=r"(r[0]), "=r"(r[1]), "=r"(r[2]), "=r"(r[3]) : "r"(addr));
}
__device__ __forceinline__ void cpa16(uint32_t dst, const void* src) {
    asm volatile("cp.async.cg.shared.global [%0], [%1], 16;" :: "r"(dst), "l"(src));
}
__device__ __forceinline__ void cpa_commit() { asm volatile("cp.async.commit_group;"); }
template <int N>
__device__ __forceinline__ void cpa_wait() {
    asm volatile("cp.async.wait_group %0;" :: "n"(N));
}

// ---------------------------------------------------------------------------
// Pre-pass 1: elementwise tf32 rounding (x -> g_xtf), float4 vectorized.
// ---------------------------------------------------------------------------
__global__ void cvt_tf32_kernel(const float* __restrict__ in,
                                float* __restrict__ out, int n4) {
    int i = blockIdx.x * blockDim.x + threadIdx.x;
    if (i < n4) {
        float4 v = reinterpret_cast<const float4*>(in)[i];
        v.x = __uint_as_float(f2tf(v.x));
        v.y = __uint_as_float(f2tf(v.y));
        v.z = __uint_as_float(f2tf(v.z));
        v.w = __uint_as_float(f2tf(v.w));
        reinterpret_cast<float4*>(out)[i] = v;
    }
}

// ---------------------------------------------------------------------------
// Pre-pass 2: WT[C][R] = tf32(W[R][C])
// ---------------------------------------------------------------------------
__global__ void transpose_cvt_kernel(const float* __restrict__ W,
                                     float* __restrict__ WT, int R, int C) {
    __shared__ float t[32][33];
    int c0 = blockIdx.x * 32, r0 = blockIdx.y * 32;
    int x = threadIdx.x, y = threadIdx.y;   // block (32, 8)
    #pragma unroll
    for (int i = 0; i < 32; i += 8)
        t[y + i][x] = __uint_as_float(f2tf(W[(size_t)(r0 + y + i) * C + c0 + x]));
    __syncthreads();
    #pragma unroll
    for (int i = 0; i < 32; i += 8)
        WT[(size_t)(c0 + y + i) * R + r0 + x] = t[x][y + i];
}

// ---------------------------------------------------------------------------
// GEMM: C[M,N] = A[M,K] * BT[N,K] (+bias). A,BT already tf32 values.
// Block 128x128, BK=32, 256 thr, 8 warps (2m x 4n), warp tile 64x32.
// 3-stage cp.async pipeline, ONE __syncthreads per iter, ldmatrix frags.
// Loads for chunk it+2 issue after barrier(it): every warp past that barrier
// finished compute(it-1), the last reader of stage (it+2)%3 — race-free.
// ---------------------------------------------------------------------------
template <bool BIAS, bool CVTOUT>
__global__ __launch_bounds__(256, 2) void gemm_kernel(
    const float* __restrict__ A, const float* __restrict__ BT,
    const float* __restrict__ bias, float* __restrict__ C, int N, int K)
{
    extern __shared__ float sm[];
    const uint32_t STG = 128 * 36 * 2 * 4;   // bytes per stage (A tile + B tile)
    const uint32_t BOF = 128 * 36 * 4;       // B offset within a stage

    const int tid  = threadIdx.x;
    const int lane = tid & 31;
    const int warp = tid >> 5;
    const int g    = lane >> 2;
    const int cc   = lane & 3;
    const int wr   = warp >> 2;     // 0..1
    const int wc   = warp & 3;      // 0..3
    const int bm   = blockIdx.y * 128;
    const int bn   = blockIdx.x * 128;

    const uint32_t smb = (uint32_t)__cvta_generic_to_shared(sm);

    const int ldrow = tid >> 3;
    const int ldcol = (tid & 7) * 4;
    const uint32_t aDst = smb + (ldrow * 36 + ldcol) * 4;
    const uint32_t bDst = aDst + BOF;
    const float* aSrc = A  + (size_t)(bm + ldrow) * K + ldcol;
    const float* bSrc = BT + (size_t)(bn + ldrow) * K + ldcol;

    const int rowpat = (lane & 7) + ((lane >> 3) & 1) * 8;
    const int colpat = (lane >> 4) * 4;
    uint32_t aLd[4], bLd[2];
    #pragma unroll
    for (int mt = 0; mt < 4; mt++)
        aLd[mt] = smb + ((wr * 64 + mt * 16 + rowpat) * 36 + colpat) * 4;
    #pragma unroll
    for (int np = 0; np < 2; np++)
        bLd[np] = smb + BOF + ((wc * 32 + np * 16 + rowpat) * 36 + colpat) * 4;

    float acc[4][4][4];
    #pragma unroll
    for (int mt = 0; mt < 4; mt++)
        #pragma unroll
        for (int nt = 0; nt < 4; nt++)
            #pragma unroll
            for (int r = 0; r < 4; r++) acc[mt][nt][r] = 0.f;

    const int NIT = K >> 5;

    // load chunk c into stage c%3
    auto load_chunk = [&](int c) {
        const uint32_t so = (uint32_t)(c % 3) * STG;
        const int ko = c * 32;
        #pragma unroll
        for (int i = 0; i < 4; i++)
            cpa16(aDst + so + i * 4608, aSrc + (size_t)i * 32 * K + ko);
        #pragma unroll
        for (int i = 0; i < 4; i++)
            cpa16(bDst + so + i * 4608, bSrc + (size_t)i * 32 * K + ko);
        cpa_commit();
    };

    load_chunk(0);
    load_chunk(1);

    for (int it = 0; it < NIT; ++it) {
        if (it + 1 < NIT) cpa_wait<1>(); else cpa_wait<0>();
        __syncthreads();
        if (it + 2 < NIT) load_chunk(it + 2);

        const uint32_t st = (uint32_t)(it % 3) * STG;
        #pragma unroll
        for (int kk = 0; kk < 4; kk++) {
            uint32_t af[4][4], bq[2][4];
            #pragma unroll
            for (int mt = 0; mt < 4; mt++) ldsm4(aLd[mt] + st + kk * 32, af[mt]);
            ldsm4(bLd[0] + st + kk * 32, bq[0]);
            ldsm4(bLd[1] + st + kk * 32, bq[1]);
            #pragma unroll
            for (int mt = 0; mt < 4; mt++) {
                mma8(acc[mt][0], af[mt], bq[0][0], bq[0][2]);
                mma8(acc[mt][1], af[mt], bq[0][1], bq[0][3]);
                mma8(acc[mt][2], af[mt], bq[1][0], bq[1][2]);
                mma8(acc[mt][3], af[mt], bq[1][1], bq[1][3]);
            }
        }
    }

    #pragma unroll
    for (int mt = 0; mt < 4; mt++) {
        #pragma unroll
        for (int nt = 0; nt < 4; nt++) {
            int row = bm + wr * 64 + mt * 16 + g;
            int col = bn + wc * 32 + nt * 8 + cc * 2;
            float b0 = 0.f, b1 = 0.f;
            if (BIAS) { b0 = bias[col]; b1 = bias[col + 1]; }
            float2 v0, v1;
            if (CVTOUT) {
                v0 = make_float2(__uint_as_float(f2tf(acc[mt][nt][0] + b0)),
                                 __uint_as_float(f2tf(acc[mt][nt][1] + b1)));
                v1 = make_float2(__uint_as_float(f2tf(acc[mt][nt][2] + b0)),
                                 __uint_as_float(f2tf(acc[mt][nt][3] + b1)));
            } else {
                v0 = make_float2(acc[mt][nt][0] + b0, acc[mt][nt][1] + b1);
                v1 = make_float2(acc[mt][nt][2] + b0, acc[mt][nt][3] + b1);
            }
            *reinterpret_cast<float2*>(&C[(size_t)row * N + col])       = v0;
            *reinterpret_cast<float2*>(&C[(size_t)(row + 8) * N + col]) = v1;
        }
    }
}

// ---------------------------------------------------------------------------
// Local attention, one block per (hq, head, b). 4 warps x 16 q-cols.
// qkv already tf32-valued -> fills are pure cp.async copies.
// Q scale (x0.125, exact pow2) applied to fragments in registers.
// K/Q/P smem stride 68 (LDSM-friendly); V stride 72 (conflict-free scalar LDS).
// ---------------------------------------------------------------------------
__global__ __launch_bounds__(128) void attn_kernel(
    const float* __restrict__ qkv, float* __restrict__ attout)
{
    extern __shared__ float sm[];
    float* Vs = sm + 2 * 64 * 68;    // 64*72

    const int tid  = threadIdx.x;
    const int lane = tid & 31;
    const int warp = tid >> 5;
    const int g    = lane >> 2;
    const int cc   = lane & 3;
    const int hq   = blockIdx.x;
    const int head = blockIdx.y;
    const int b    = blockIdx.z;
    const int qrow = warp * 16;
    const int k0   = (qrow - 8 < 0) ? 0 : (qrow - 8 > 32 ? 32 : qrow - 8);

    const uint32_t smb = (uint32_t)__cvta_generic_to_shared(sm);
    const int rowpat = (lane & 7) + ((lane >> 3) & 1) * 8;
    const int colpat = (lane >> 4) * 4;
    const uint32_t ksB = smb + (64 * 68) * 4;
    const uint32_t vsB = smb + (2 * 64 * 68) * 4;
    uint32_t kAddr[2];
    #pragma unroll
    for (int np = 0; np < 2; np++)
        kAddr[np] = ksB + ((k0 + np * 16 + rowpat) * 68 + colpat) * 4;
    const uint32_t pAddr = smb + ((qrow + rowpat) * 68 + colpat) * 4;

    const int frow = tid >> 4;          // +8 per iter
    const int fcol = (tid & 15) * 4;

    // ---- Load Q via cp.async (already tf32) ----
    {
        const float* qb = qkv + ((size_t)(b * NTOK + hq * 64)) * QKVC + head * 64;
        #pragma unroll
        for (int i = 0; i < 8; i++)
            cpa16(smb + (((frow + i * 8) * 68 + fcol) * 4),
                  qb + (size_t)(frow + i * 8) * QKVC + fcol);
        cpa_commit();
        cpa_wait<0>();
    }
    __syncthreads();

    uint32_t qa[8][4];
    #pragma unroll
    for (int kk = 0; kk < 8; kk++) {
        ldsm4(pAddr + kk * 32, qa[kk]);
        #pragma unroll
        for (int r = 0; r < 4; r++)
            qa[kk][r] = __float_as_uint(__uint_as_float(qa[kk][r]) * 0.125f);
    }
    __syncthreads();                 // Qs free -> P buffer

    float o[8][4];
    #pragma unroll
    for (int nt = 0; nt < 8; nt++)
        #pragma unroll
        for (int r = 0; r < 4; r++) o[nt][r] = 0.f;
    float mrun[2] = {-1e30f, -1e30f};
    float lrun[2] = {0.f, 0.f};

    const int kh0 = (hq - 3 > 0)  ? hq - 3 : 0;
    const int kh1 = (hq + 3 < 15) ? hq + 3 : 15;

    for (int kh = kh0; kh <= kh1; kh++) {
        const float* kb = qkv + ((size_t)(b * NTOK + kh * 64)) * QKVC + DIMSZ + head * 64;
        const float* vb = kb + DIMSZ;
        #pragma unroll
        for (int i = 0; i < 8; i++) {
            const size_t goff = (size_t)(frow + i * 8) * QKVC + fcol;
            cpa16(ksB + (((frow + i * 8) * 68 + fcol) * 4), kb + goff);
            cpa16(vsB + (((frow + i * 8) * 72 + fcol) * 4), vb + goff);
        }
        cpa_commit();
        cpa_wait<0>();
        __syncthreads();

        // ---- S = Q K^T over this warp's 32-key window ----
        float s[4][4];
        #pragma unroll
        for (int nt = 0; nt < 4; nt++)
            #pragma unroll
            for (int r = 0; r < 4; r++) s[nt][r] = 0.f;

        #pragma unroll
        for (int kk = 0; kk < 8; kk++) {
            #pragma unroll
            for (int np = 0; np < 2; np++) {
                uint32_t kq[4];
                ldsm4(kAddr[np] + kk * 32, kq);
                mma8(s[2 * np    ], qa[kk], kq[0], kq[2]);
                mma8(s[2 * np + 1], qa[kk], kq[1], kq[3]);
            }
        }

        // ---- Mask + online softmax ----
        float mloc[2] = {mrun[0], mrun[1]};
        #pragma unroll
        for (int nt = 0; nt < 4; nt++) {
            #pragma unroll
            for (int r = 0; r < 4; r++) {
                int qw = qrow + g + ((r >> 1) << 3);
                int kw = k0 + nt * 8 + cc * 2 + (r & 1);
                int d  = qw - kw;
                if (d > 5 || d < -5) s[nt][r] = -1e30f;
                mloc[r >> 1] = fmaxf(mloc[r >> 1], s[nt][r]);
            }
        }
        #pragma unroll
        for (int h = 0; h < 2; h++) {
            mloc[h] = fmaxf(mloc[h], __shfl_xor_sync(0xffffffffu, mloc[h], 1));
            mloc[h] = fmaxf(mloc[h], __shfl_xor_sync(0xffffffffu, mloc[h], 2));
        }
        float alpha[2];
        #pragma unroll
        for (int h = 0; h < 2; h++) {
            alpha[h] = __expf(mrun[h] - mloc[h]);
            mrun[h]  = mloc[h];
        }
        float rs[2] = {0.f, 0.f};
        #pragma unroll
        for (int nt = 0; nt < 4; nt++) {
            #pragma unroll
            for (int r = 0; r < 4; r++) {
                float p = __expf(s[nt][r] - mrun[r >> 1]);
                s[nt][r] = p;
                rs[r >> 1] += p;
            }
        }
        #pragma unroll
        for (int h = 0; h < 2; h++) {
            rs[h] += __shfl_xor_sync(0xffffffffu, rs[h], 1);
            rs[h] += __shfl_xor_sync(0xffffffffu, rs[h], 2);
            lrun[h] = lrun[h] * alpha[h] + rs[h];
        }
        #pragma unroll
        for (int nt = 0; nt < 8; nt++)
            #pragma unroll
            for (int r = 0; r < 4; r++) o[nt][r] *= alpha[r >> 1];

        // ---- P (16x32, window-relative cols) -> smem -> A-frags ----
        float* Ps = sm;
        #pragma unroll
        for (int nt = 0; nt < 4; nt++) {
            float2 p0 = make_float2(__uint_as_float(f2tf(s[nt][0])),
                                    __uint_as_float(f2tf(s[nt][1])));
            float2 p1 = make_float2(__uint_as_float(f2tf(s[nt][2])),
                                    __uint_as_float(f2tf(s[nt][3])));
            *reinterpret_cast<float2*>(&Ps[(qrow + g    ) * 68 + nt * 8 + cc * 2]) = p0;
            *reinterpret_cast<float2*>(&Ps[(qrow + g + 8) * 68 + nt * 8 + cc * 2]) = p1;
        }
        __syncwarp();

        // ---- O += P V  (32-key contraction, conflict-free V) ----
        #pragma unroll
        for (int kk = 0; kk < 4; kk++) {
            uint32_t pa[4];
            ldsm4(pAddr + kk * 32, pa);
            const int krow = k0 + kk * 8;
            #pragma unroll
            for (int nt = 0; nt < 8; nt++) {
                uint32_t vf0 = __float_as_uint(Vs[(krow + cc    ) * 72 + nt * 8 + g]);
                uint32_t vf1 = __float_as_uint(Vs[(krow + cc + 4) * 72 + nt * 8 + g]);
                mma8(o[nt], pa, vf0, vf1);
            }
        }
        __syncthreads();
    }

    float inv[2] = {1.f / lrun[0], 1.f / lrun[1]};
    float* ob = attout + ((size_t)(b * NTOK + hq * 64)) * DIMSZ + head * 64;
    #pragma unroll
    for (int nt = 0; nt < 8; nt++) {
        int col = nt * 8 + cc * 2;
        float2 v0 = make_float2(__uint_as_float(f2tf(o[nt][0] * inv[0])),
                                __uint_as_float(f2tf(o[nt][1] * inv[0])));
        float2 v1 = make_float2(__uint_as_float(f2tf(o[nt][2] * inv[1])),
                                __uint_as_float(f2tf(o[nt][3] * inv[1])));
        *reinterpret_cast<float2*>(&ob[(size_t)(qrow + g    ) * DIMSZ + col]) = v0;
        *reinterpret_cast<float2*>(&ob[(size_t)(qrow + g + 8) * DIMSZ + col]) = v1;
    }
}

// ---------------------------------------------------------------------------
extern "C" void kernel_launch(void* const* d_in, const int* in_sizes, int n_in,
                              void* d_out, int out_size)
{
    (void)in_sizes; (void)n_in; (void)out_size;
    const float* x      = (const float*)d_in[0];
    const float* w_qkv  = (const float*)d_in[1];
    const float* w_proj = (const float*)d_in[2];
    const float* b_proj = (const float*)d_in[3];
    float* out = (float*)d_out;

    float *qkv_ptr, *att_ptr, *xtf_ptr, *wqkvT, *wprojT;
    cudaGetSymbolAddress((void**)&qkv_ptr, g_qkv);
    cudaGetSymbolAddress((void**)&att_ptr, g_att);
    cudaGetSymbolAddress((void**)&xtf_ptr, g_xtf);
    cudaGetSymbolAddress((void**)&wqkvT, g_wqkvT);
    cudaGetSymbolAddress((void**)&wprojT, g_wprojT);

    const int gemm_smem = 3 * 2 * 128 * 36 * (int)sizeof(float);         // 110592
    const int attn_smem = (2 * 64 * 68 + 64 * 72) * (int)sizeof(float);  // 53248
    cudaFuncSetAttribute((const void*)gemm_kernel<false, true>,
                         cudaFuncAttributeMaxDynamicSharedMemorySize, gemm_smem);
    cudaFuncSetAttribute((const void*)gemm_kernel<true, false>,
                         cudaFuncAttributeMaxDynamicSharedMemorySize, gemm_smem);
    cudaFuncSetAttribute((const void*)attn_kernel,
                         cudaFuncAttributeMaxDynamicSharedMemorySize, attn_smem);

    // 0) Pre-passes: x -> tf32, weights -> transposed tf32
    const int n4 = MTOT * DIMSZ / 4;
    cvt_tf32_kernel<<<(n4 + 255) / 256, 256>>>(x, xtf_ptr, n4);
    transpose_cvt_kernel<<<dim3(QKVC / 32, DIMSZ / 32), dim3(32, 8)>>>(
        w_qkv, wqkvT, DIMSZ, QKVC);
    transpose_cvt_kernel<<<dim3(DIMSZ / 32, DIMSZ / 32), dim3(32, 8)>>>(
        w_proj, wprojT, DIMSZ, DIMSZ);

    // 1) QKV GEMM (outputs tf32-rounded)
    gemm_kernel<false, true><<<dim3(QKVC / 128, MTOT / 128), 256, gemm_smem>>>(
        xtf_ptr, wqkvT, nullptr, qkv_ptr, QKVC, DIMSZ);

    // 2) Local attention (pure-copy fills; output tf32-rounded)
    attn_kernel<<<dim3(16, 8, BATCH), 128, attn_smem>>>(qkv_ptr, att_ptr);

    // 3) Projection (plain fp32 output + bias)
    gemm_kernel<true, false><<<dim3(DIMSZ / 128, MTOT / 128), 256, gemm_smem>>>(
        att_ptr, wprojT, b_proj, out, DIMSZ, DIMSZ);
}